// round 14
// baseline (speedup 1.0000x reference)
#include <cuda_runtime.h>
#include <cuda_fp16.h>

#define NN 50000
#define NE 3200000
#define DEG_BLOCKS 645

// Scratch (device globals — no allocation allowed).
// g_degacc invariant: ZERO at entry of every kernel_launch call (zero-init at
// module load; node_kernel re-zeroes after reading). Exact-integer float adds.
__device__ float4 g_nodeF4[NN];     // pos.x, pos.y, cell, pad
__device__ uint4  g_sh[NN * 2];     // s[16] fp16, 32B/node
__device__ float4 g_yacc[NN];       // sum over edges of m@W_out
__device__ float  g_degacc[NN];     // deg + 4096*consume_deg (exact ints)
__device__ double g_red[8];         // 0:velx 1:vely 2:border 3:dead 4:consumed 5:vis_food 6:food_dist
__device__ unsigned int g_done;     // last-block ticket

// ---------------- Kernel 0: heterogeneous prep (2 thr/node) + deg counting ----------------
__global__ void __launch_bounds__(256)
prep_deg_kernel(const float* __restrict__ x,
                const int*   __restrict__ dst,
                const float* __restrict__ W_edge,
                const float* __restrict__ W_src,
                const float* __restrict__ b1,
                int n, int E, int prepBlocks)
{
    if ((int)blockIdx.x >= prepBlocks) {
        // ---- deg path: count in-degree (dst only, no gather) ----
        const int4* __restrict__ d4 = (const int4*)dst;
        int nd4 = E >> 2;
        int dtid    = ((int)blockIdx.x - prepBlocks) * 256 + threadIdx.x;
        int dstride = DEG_BLOCKS * 256;
        for (int k = dtid; k < nd4; k += dstride) {
            int4 v = __ldg(&d4[k]);
            atomicAdd(&g_degacc[v.x], 1.0f);
            atomicAdd(&g_degacc[v.y], 1.0f);
            atomicAdd(&g_degacc[v.z], 1.0f);
            atomicAdd(&g_degacc[v.w], 1.0f);
        }
        return;
    }

    // ---- prep path: 2 threads per node ----
    int t = blockIdx.x * blockDim.x + threadIdx.x;
    if (t == 0) {
        #pragma unroll
        for (int k = 0; k < 8; k++) g_red[k] = 0.0;
        g_done = 0u;
    }
    int i = t >> 1;        // node
    int q = t & 1;         // which half of the 16 hidden units
    if (i >= n) return;

    float xv[10];
    #pragma unroll
    for (int c = 0; c < 10; c++) xv[c] = __ldg(&x[i * 10 + c]);
    float cell = xv[4];

    float sv[8];
    #pragma unroll
    for (int jj = 0; jj < 8; jj++) {
        int j = q * 8 + jj;
        float acc = __ldg(&b1[j]) + cell * __ldg(&W_edge[3 * 16 + j]);
        #pragma unroll
        for (int c = 0; c < 10; c++)
            acc += xv[c] * __ldg(&W_src[c * 16 + j]);
        sv[jj] = acc;
    }

    uint4 pk;
    __half2 h0 = __floats2half2_rn(sv[0], sv[1]);
    __half2 h1 = __floats2half2_rn(sv[2], sv[3]);
    __half2 h2 = __floats2half2_rn(sv[4], sv[5]);
    __half2 h3 = __floats2half2_rn(sv[6], sv[7]);
    pk.x = *reinterpret_cast<unsigned int*>(&h0);
    pk.y = *reinterpret_cast<unsigned int*>(&h1);
    pk.z = *reinterpret_cast<unsigned int*>(&h2);
    pk.w = *reinterpret_cast<unsigned int*>(&h3);
    g_sh[i * 2 + q] = pk;

    if (q == 0) {
        g_nodeF4[i] = make_float4(xv[0], xv[1], cell, 0.0f);
        g_yacc[i]   = make_float4(0.f, 0.f, 0.f, 0.f);
        // g_degacc NOT zeroed here — rotating invariant (deg blocks RED into it now)
    }
}

// ---------------- Kernel 1: edge kernel (2 edges/thread, smem weights, no deg atomic) ----------------
__global__ void __launch_bounds__(256)
edge_kernel(const int* __restrict__ src,
            const int* __restrict__ dst,
            const float* __restrict__ W_edge,
            const float* __restrict__ W_out,
            int E)
{
    __shared__ float4 sWe[16];   // (wA, wB, wC, 0) per hidden unit
    __shared__ float4 sWo[16];   // W_out row per hidden unit

    if (threadIdx.x < 16) {
        int j = threadIdx.x;
        sWe[j] = make_float4(__ldg(&W_edge[0 * 16 + j]),
                             __ldg(&W_edge[1 * 16 + j]),
                             __ldg(&W_edge[2 * 16 + j]),
                             0.0f);
        sWo[j] = __ldg((const float4*)&W_out[j * 4]);
    }
    __syncthreads();

    const float4* __restrict__ nf  = g_nodeF4;
    const uint4*  __restrict__ spv = g_sh;
    const int2*   __restrict__ s2  = (const int2*)src;
    const int2*   __restrict__ d2v = (const int2*)dst;

    float vf = 0.f;   // visible_food count
    float fd = 0.f;   // food dist sum

    int P = E >> 1;   // edge pairs (E is even)
    int stride = gridDim.x * blockDim.x;
    for (int p = blockIdx.x * blockDim.x + threadIdx.x; p < P; p += stride) {
        int2 sp = __ldg(&s2[p]);
        int2 dp = __ldg(&d2v[p]);

        // issue ALL gathers up front (8 independent LDG.128)
        float4 nsa = __ldg(&nf[sp.x]);
        float4 nda = __ldg(&nf[dp.x]);
        uint4  pa0 = __ldg(&spv[sp.x * 2 + 0]);
        uint4  pa1 = __ldg(&spv[sp.x * 2 + 1]);
        float4 nsb = __ldg(&nf[sp.y]);
        float4 ndb = __ldg(&nf[dp.y]);
        uint4  pb0 = __ldg(&spv[sp.y * 2 + 0]);
        uint4  pb1 = __ldg(&spv[sp.y * 2 + 1]);

        float dxa = nsa.x - nda.x;
        float dya = nsa.y - nda.y;
        float dista = sqrtf(__fadd_rn(__fadd_rn(__fmul_rn(dxa, dxa), __fmul_rn(dya, dya)), 1e-12f));
        float dxb = nsb.x - ndb.x;
        float dyb = nsb.y - ndb.y;
        float distb = sqrtf(__fadd_rn(__fadd_rn(__fmul_rn(dxb, dxb), __fmul_rn(dyb, dyb)), 1e-12f));

        unsigned int pka[8] = {pa0.x, pa0.y, pa0.z, pa0.w, pa1.x, pa1.y, pa1.z, pa1.w};
        unsigned int pkb[8] = {pb0.x, pb0.y, pb0.z, pb0.w, pb1.x, pb1.y, pb1.z, pb1.w};

        float ya0 = 0.f, ya1 = 0.f, ya2 = 0.f, ya3 = 0.f;
        float yb0 = 0.f, yb1 = 0.f, yb2 = 0.f, yb3 = 0.f;

        #pragma unroll
        for (int q = 0; q < 8; q++) {
            float2 fa = __half22float2(*reinterpret_cast<__half2*>(&pka[q]));
            float2 fb = __half22float2(*reinterpret_cast<__half2*>(&pkb[q]));
            int j0 = q * 2, j1 = q * 2 + 1;
            float4 we0 = sWe[j0];
            float4 we1 = sWe[j1];
            float4 wo0 = sWo[j0];
            float4 wo1 = sWo[j1];

            float ga0 = fa.x + dista * we0.x + dxa * we0.y + dya * we0.z;
            float ga1 = fa.y + dista * we1.x + dxa * we1.y + dya * we1.z;
            float gb0 = fb.x + distb * we0.x + dxb * we0.y + dyb * we0.z;
            float gb1 = fb.y + distb * we1.x + dxb * we1.y + dyb * we1.z;
            float ma0 = fmaxf(ga0, 0.f);
            float ma1 = fmaxf(ga1, 0.f);
            float mb0 = fmaxf(gb0, 0.f);
            float mb1 = fmaxf(gb1, 0.f);

            ya0 += ma0 * wo0.x + ma1 * wo1.x;
            ya1 += ma0 * wo0.y + ma1 * wo1.y;
            ya2 += ma0 * wo0.z + ma1 * wo1.z;
            ya3 += ma0 * wo0.w + ma1 * wo1.w;
            yb0 += mb0 * wo0.x + mb1 * wo1.x;
            yb1 += mb0 * wo0.y + mb1 * wo1.y;
            yb2 += mb0 * wo0.z + mb1 * wo1.z;
            yb3 += mb0 * wo0.w + mb1 * wo1.w;
        }

        float4* ypa = &g_yacc[dp.x];
        asm volatile("red.global.add.v4.f32 [%0], {%1,%2,%3,%4};"
                     :: "l"(ypa), "f"(ya0), "f"(ya1), "f"(ya2), "f"(ya3) : "memory");
        bool consumea = (dista < 0.05f) && (nsa.z == 1.0f) && (nda.z == 0.0f);
        if (consumea) atomicAdd(&g_degacc[dp.x], 4096.0f);   // rare: ~3e-4 of edges
        if (nsa.z == 0.0f) { vf += 1.0f; fd += dista; }

        float4* ypb = &g_yacc[dp.y];
        asm volatile("red.global.add.v4.f32 [%0], {%1,%2,%3,%4};"
                     :: "l"(ypb), "f"(yb0), "f"(yb1), "f"(yb2), "f"(yb3) : "memory");
        bool consumeb = (distb < 0.05f) && (nsb.z == 1.0f) && (ndb.z == 0.0f);
        if (consumeb) atomicAdd(&g_degacc[dp.y], 4096.0f);
        if (nsb.z == 0.0f) { vf += 1.0f; fd += distb; }
    }

    // warp reduce, lane0 -> double atomics
    #pragma unroll
    for (int o = 16; o > 0; o >>= 1) {
        vf += __shfl_down_sync(0xffffffffu, vf, o);
        fd += __shfl_down_sync(0xffffffffu, fd, o);
    }
    if ((threadIdx.x & 31) == 0) {
        atomicAdd(&g_red[5], (double)vf);
        atomicAdd(&g_red[6], (double)fd);
    }
}

// ---------------- Kernel 2: node finalize + degacc re-zero + last-block scalars ----------------
__global__ void __launch_bounds__(256)
node_kernel(const float* __restrict__ x,
            const float* __restrict__ noise,
            const float* __restrict__ b2,
            float* __restrict__ out,
            int n, int keepBase, int scalarBase, float invN)
{
    int i = blockIdx.x * blockDim.x + threadIdx.x;

    float velx = 0.f, vely = 0.f, border = 0.f, deadf = 0.f, consf = 0.f;

    if (i < n) {
        float4 y   = g_yacc[i];
        float pack = g_degacc[i];
        g_degacc[i] = 0.0f;     // restore rotating invariant for next call

        float xv[10];
        #pragma unroll
        for (int c = 0; c < 10; c++) xv[c] = __ldg(&x[i * 10 + c]);
        float cell = xv[4];
        float cm = (cell == 1.0f) ? 1.0f : 0.0f;

        float h0 = tanhf(y.x + __ldg(&b2[0])) * cm;
        float h1 = tanhf(y.y + __ldg(&b2[1])) * cm;
        float h2 = tanhf(y.z + __ldg(&b2[2])) * cm;
        float h3 = tanhf(y.w + __ldg(&b2[3])) * cm;

        float nvx = fminf(fmaxf(xv[2] + h0 * 0.005f, -0.02f), 0.02f);
        float nvy = fminf(fmaxf(xv[3] + h1 * 0.005f, -0.02f), 0.02f);
        float npx = xv[0] + nvx;
        float npy = xv[1] + nvy;

        float nzx = nvx + (__ldg(&noise[2 * i])     * 2.0f - 1.0f) * 0.004f * cm;
        float nzy = nvy + (__ldg(&noise[2 * i + 1]) * 2.0f - 1.0f) * 0.004f * cm;

        float* o = out + (size_t)i * 10;
        o[0] = npx; o[1] = npy; o[2] = nzx; o[3] = nzy; o[4] = cell;
        o[5] = h2;  o[6] = h3;  o[7] = xv[7]; o[8] = xv[8]; o[9] = xv[9];

        int pi   = (int)pack;
        int deg  = pi & 4095;
        int cdeg = pi >> 12;
        bool dead     = (cell == 1.0f) && (deg < 3);
        bool consumed = (cell == 0.0f) && (cdeg >= 3);
        out[keepBase + i] = (dead || consumed) ? 0.0f : 1.0f;

        velx = fabsf(nvx);
        vely = fabsf(nvy);
        float apx = fabsf(npx);
        if (apx > 1.0f) border += logf(apx + 1e-6f);
        float apy = fabsf(npy);
        if (apy > 1.0f) border += logf(apy + 1e-6f);
        deadf = dead ? 1.0f : 0.0f;
        consf = consumed ? 1.0f : 0.0f;
    }

    #pragma unroll
    for (int o = 16; o > 0; o >>= 1) {
        velx   += __shfl_down_sync(0xffffffffu, velx,   o);
        vely   += __shfl_down_sync(0xffffffffu, vely,   o);
        border += __shfl_down_sync(0xffffffffu, border, o);
        deadf  += __shfl_down_sync(0xffffffffu, deadf,  o);
        consf  += __shfl_down_sync(0xffffffffu, consf,  o);
    }
    if ((threadIdx.x & 31) == 0) {
        atomicAdd(&g_red[0], (double)velx);
        atomicAdd(&g_red[1], (double)vely);
        atomicAdd(&g_red[2], (double)border);
        atomicAdd(&g_red[3], (double)deadf);
        atomicAdd(&g_red[4], (double)consf);
    }

    // last block writes the 7 scalar outputs
    __syncthreads();
    if (threadIdx.x == 0) {
        __threadfence();
        unsigned int t = atomicAdd(&g_done, 1u);
        if (t == gridDim.x - 1) {
            volatile double* r = g_red;
            out[scalarBase + 0] = (float)r[0] * invN;   // velocity_bonus x (mean)
            out[scalarBase + 1] = (float)r[1] * invN;   // velocity_bonus y
            out[scalarBase + 2] = (float)r[2];          // border_cost
            out[scalarBase + 3] = (float)r[4];          // food_reward
            out[scalarBase + 4] = (float)r[3];          // dead_cost
            out[scalarBase + 5] = (float)r[5];          // visible_food
            out[scalarBase + 6] = (float)r[6];          // mean_food_dist (sum)
        }
    }
}

extern "C" void kernel_launch(void* const* d_in, const int* in_sizes, int n_in,
                              void* d_out, int out_size)
{
    const float* x      = (const float*)d_in[0];
    const int*   src    = (const int*)  d_in[1];
    const int*   dst    = (const int*)  d_in[2];
    const float* noise  = (const float*)d_in[3];
    const float* W_edge = (const float*)d_in[4];
    const float* W_src  = (const float*)d_in[5];
    const float* b1     = (const float*)d_in[6];
    const float* W_out  = (const float*)d_in[7];
    const float* b2     = (const float*)d_in[8];

    int n = in_sizes[0] / 10;
    int E = in_sizes[1];
    float* out = (float*)d_out;

    int scalarBase = out_size - 7;
    int keepBase   = scalarBase - n;

    int prepBlocks = (2 * n + 255) / 256;

    prep_deg_kernel<<<prepBlocks + DEG_BLOCKS, 256>>>(x, dst, W_edge, W_src, b1,
                                                      n, E, prepBlocks);
    edge_kernel<<<592, 256>>>(src, dst, W_edge, W_out, E);
    node_kernel<<<(n + 255) / 256, 256>>>(x, noise, b2, out, n, keepBase,
                                          scalarBase, 1.0f / (float)n);
}

// round 15
// speedup vs baseline: 1.1859x; 1.1859x over previous
#include <cuda_runtime.h>
#include <cuda_fp16.h>

#define NN 50000
#define NE 3200000

// Scratch (device globals — no allocation allowed)
__device__ float4 g_nodeF4[NN];     // pos.x, pos.y, cell, pad
__device__ uint4  g_sh[NN * 2];     // s[16] fp16, 32B/node
__device__ float4 g_yacc[NN];       // sum over edges of m@W_out
__device__ float  g_degacc[NN];     // deg + 4096*consume_deg (exact ints)
__device__ double g_red[8];         // 0:velx 1:vely 2:border 3:dead 4:consumed 5:vis_food 6:food_dist

// ---------------- Kernel 0: per-node prep + all zeroing (fused) ----------------
__global__ void prep_kernel(const float* __restrict__ x,
                            const float* __restrict__ W_edge,
                            const float* __restrict__ W_src,
                            const float* __restrict__ b1,
                            int n)
{
    int i = blockIdx.x * blockDim.x + threadIdx.x;
    if (i == 0) {
        #pragma unroll
        for (int k = 0; k < 8; k++) g_red[k] = 0.0;
    }
    if (i >= n) return;

    float xv[10];
    #pragma unroll
    for (int c = 0; c < 10; c++) xv[c] = __ldg(&x[i * 10 + c]);
    float cell = xv[4];

    // s_j = b1_j + cell*W_edge[3][j] + sum_c x_c * W_src[c][j]  -> fp16
    float sv[16];
    #pragma unroll
    for (int j = 0; j < 16; j++) {
        float acc = __ldg(&b1[j]) + cell * __ldg(&W_edge[3 * 16 + j]);
        #pragma unroll
        for (int c = 0; c < 10; c++)
            acc += xv[c] * __ldg(&W_src[c * 16 + j]);
        sv[j] = acc;
    }

    #pragma unroll
    for (int q = 0; q < 2; q++) {
        uint4 pk;
        __half2 h0 = __floats2half2_rn(sv[q * 8 + 0], sv[q * 8 + 1]);
        __half2 h1 = __floats2half2_rn(sv[q * 8 + 2], sv[q * 8 + 3]);
        __half2 h2 = __floats2half2_rn(sv[q * 8 + 4], sv[q * 8 + 5]);
        __half2 h3 = __floats2half2_rn(sv[q * 8 + 6], sv[q * 8 + 7]);
        pk.x = *reinterpret_cast<unsigned int*>(&h0);
        pk.y = *reinterpret_cast<unsigned int*>(&h1);
        pk.z = *reinterpret_cast<unsigned int*>(&h2);
        pk.w = *reinterpret_cast<unsigned int*>(&h3);
        g_sh[i * 2 + q] = pk;
    }
    g_nodeF4[i]  = make_float4(xv[0], xv[1], cell, 0.0f);
    g_yacc[i]    = make_float4(0.f, 0.f, 0.f, 0.f);
    g_degacc[i]  = 0.f;
}

// ---------------- Kernel 1: edge kernel (2 edges/thread, smem weights) ----------------
__global__ void __launch_bounds__(256)
edge_kernel(const int* __restrict__ src,
            const int* __restrict__ dst,
            const float* __restrict__ W_edge,
            const float* __restrict__ W_out,
            int E)
{
    __shared__ float4 sWe[16];   // (wA, wB, wC, 0) per hidden unit
    __shared__ float4 sWo[16];   // W_out row per hidden unit

    if (threadIdx.x < 16) {
        int j = threadIdx.x;
        sWe[j] = make_float4(__ldg(&W_edge[0 * 16 + j]),
                             __ldg(&W_edge[1 * 16 + j]),
                             __ldg(&W_edge[2 * 16 + j]),
                             0.0f);
        sWo[j] = __ldg((const float4*)&W_out[j * 4]);
    }
    __syncthreads();

    const float4* __restrict__ nf  = g_nodeF4;
    const uint4*  __restrict__ spv = g_sh;
    const int2*   __restrict__ s2  = (const int2*)src;
    const int2*   __restrict__ d2v = (const int2*)dst;

    float vf = 0.f;   // visible_food count
    float fd = 0.f;   // food dist sum

    int P = E >> 1;   // edge pairs (E is even)
    int stride = gridDim.x * blockDim.x;
    for (int p = blockIdx.x * blockDim.x + threadIdx.x; p < P; p += stride) {
        int2 sp = __ldg(&s2[p]);
        int2 dp = __ldg(&d2v[p]);

        // issue ALL gathers up front (8 independent LDG.128)
        float4 nsa = __ldg(&nf[sp.x]);
        float4 nda = __ldg(&nf[dp.x]);
        uint4  pa0 = __ldg(&spv[sp.x * 2 + 0]);
        uint4  pa1 = __ldg(&spv[sp.x * 2 + 1]);
        float4 nsb = __ldg(&nf[sp.y]);
        float4 ndb = __ldg(&nf[dp.y]);
        uint4  pb0 = __ldg(&spv[sp.y * 2 + 0]);
        uint4  pb1 = __ldg(&spv[sp.y * 2 + 1]);

        float dxa = nsa.x - nda.x;
        float dya = nsa.y - nda.y;
        float dista = sqrtf(__fadd_rn(__fadd_rn(__fmul_rn(dxa, dxa), __fmul_rn(dya, dya)), 1e-12f));
        float dxb = nsb.x - ndb.x;
        float dyb = nsb.y - ndb.y;
        float distb = sqrtf(__fadd_rn(__fadd_rn(__fmul_rn(dxb, dxb), __fmul_rn(dyb, dyb)), 1e-12f));

        unsigned int pka[8] = {pa0.x, pa0.y, pa0.z, pa0.w, pa1.x, pa1.y, pa1.z, pa1.w};
        unsigned int pkb[8] = {pb0.x, pb0.y, pb0.z, pb0.w, pb1.x, pb1.y, pb1.z, pb1.w};

        float ya0 = 0.f, ya1 = 0.f, ya2 = 0.f, ya3 = 0.f;
        float yb0 = 0.f, yb1 = 0.f, yb2 = 0.f, yb3 = 0.f;

        // joint MLP loop: each weight LDS broadcast serves both edges
        #pragma unroll
        for (int q = 0; q < 8; q++) {
            float2 fa = __half22float2(*reinterpret_cast<__half2*>(&pka[q]));
            float2 fb = __half22float2(*reinterpret_cast<__half2*>(&pkb[q]));
            int j0 = q * 2, j1 = q * 2 + 1;
            float4 we0 = sWe[j0];
            float4 we1 = sWe[j1];
            float4 wo0 = sWo[j0];
            float4 wo1 = sWo[j1];

            float ga0 = fa.x + dista * we0.x + dxa * we0.y + dya * we0.z;
            float ga1 = fa.y + dista * we1.x + dxa * we1.y + dya * we1.z;
            float gb0 = fb.x + distb * we0.x + dxb * we0.y + dyb * we0.z;
            float gb1 = fb.y + distb * we1.x + dxb * we1.y + dyb * we1.z;
            float ma0 = fmaxf(ga0, 0.f);
            float ma1 = fmaxf(ga1, 0.f);
            float mb0 = fmaxf(gb0, 0.f);
            float mb1 = fmaxf(gb1, 0.f);

            ya0 += ma0 * wo0.x + ma1 * wo1.x;
            ya1 += ma0 * wo0.y + ma1 * wo1.y;
            ya2 += ma0 * wo0.z + ma1 * wo1.z;
            ya3 += ma0 * wo0.w + ma1 * wo1.w;
            yb0 += mb0 * wo0.x + mb1 * wo1.x;
            yb1 += mb0 * wo0.y + mb1 * wo1.y;
            yb2 += mb0 * wo0.z + mb1 * wo1.z;
            yb3 += mb0 * wo0.w + mb1 * wo1.w;
        }

        float4* ypa = &g_yacc[dp.x];
        asm volatile("red.global.add.v4.f32 [%0], {%1,%2,%3,%4};"
                     :: "l"(ypa), "f"(ya0), "f"(ya1), "f"(ya2), "f"(ya3) : "memory");
        bool consumea = (dista < 0.05f) && (nsa.z == 1.0f) && (nda.z == 0.0f);
        atomicAdd(&g_degacc[dp.x], consumea ? 4097.0f : 1.0f);
        if (nsa.z == 0.0f) { vf += 1.0f; fd += dista; }

        float4* ypb = &g_yacc[dp.y];
        asm volatile("red.global.add.v4.f32 [%0], {%1,%2,%3,%4};"
                     :: "l"(ypb), "f"(yb0), "f"(yb1), "f"(yb2), "f"(yb3) : "memory");
        bool consumeb = (distb < 0.05f) && (nsb.z == 1.0f) && (ndb.z == 0.0f);
        atomicAdd(&g_degacc[dp.y], consumeb ? 4097.0f : 1.0f);
        if (nsb.z == 0.0f) { vf += 1.0f; fd += distb; }
    }

    // warp reduce, lane0 -> double atomics
    #pragma unroll
    for (int o = 16; o > 0; o >>= 1) {
        vf += __shfl_down_sync(0xffffffffu, vf, o);
        fd += __shfl_down_sync(0xffffffffu, fd, o);
    }
    if ((threadIdx.x & 31) == 0) {
        atomicAdd(&g_red[5], (double)vf);
        atomicAdd(&g_red[6], (double)fd);
    }
}

// ---------------- Kernel 2: node finalize ----------------
__global__ void node_kernel(const float* __restrict__ x,
                            const float* __restrict__ noise,
                            const float* __restrict__ b2,
                            float* __restrict__ out,
                            int n, int keepBase)
{
    int i = blockIdx.x * blockDim.x + threadIdx.x;

    float velx = 0.f, vely = 0.f, border = 0.f, deadf = 0.f, consf = 0.f;

    if (i < n) {
        float4 y   = g_yacc[i];
        float pack = g_degacc[i];

        float xv[10];
        #pragma unroll
        for (int c = 0; c < 10; c++) xv[c] = __ldg(&x[i * 10 + c]);
        float cell = xv[4];
        float cm = (cell == 1.0f) ? 1.0f : 0.0f;

        float h0 = tanhf(y.x + __ldg(&b2[0])) * cm;
        float h1 = tanhf(y.y + __ldg(&b2[1])) * cm;
        float h2 = tanhf(y.z + __ldg(&b2[2])) * cm;
        float h3 = tanhf(y.w + __ldg(&b2[3])) * cm;

        float nvx = fminf(fmaxf(xv[2] + h0 * 0.005f, -0.02f), 0.02f);
        float nvy = fminf(fmaxf(xv[3] + h1 * 0.005f, -0.02f), 0.02f);
        float npx = xv[0] + nvx;
        float npy = xv[1] + nvy;

        float nzx = nvx + (__ldg(&noise[2 * i])     * 2.0f - 1.0f) * 0.004f * cm;
        float nzy = nvy + (__ldg(&noise[2 * i + 1]) * 2.0f - 1.0f) * 0.004f * cm;

        float* o = out + (size_t)i * 10;
        o[0] = npx; o[1] = npy; o[2] = nzx; o[3] = nzy; o[4] = cell;
        o[5] = h2;  o[6] = h3;  o[7] = xv[7]; o[8] = xv[8]; o[9] = xv[9];

        int pi   = (int)pack;
        int deg  = pi & 4095;
        int cdeg = pi >> 12;
        bool dead     = (cell == 1.0f) && (deg < 3);
        bool consumed = (cell == 0.0f) && (cdeg >= 3);
        out[keepBase + i] = (dead || consumed) ? 0.0f : 1.0f;

        velx = fabsf(nvx);
        vely = fabsf(nvy);
        float apx = fabsf(npx);
        if (apx > 1.0f) border += logf(apx + 1e-6f);
        float apy = fabsf(npy);
        if (apy > 1.0f) border += logf(apy + 1e-6f);
        deadf = dead ? 1.0f : 0.0f;
        consf = consumed ? 1.0f : 0.0f;
    }

    #pragma unroll
    for (int o = 16; o > 0; o >>= 1) {
        velx   += __shfl_down_sync(0xffffffffu, velx,   o);
        vely   += __shfl_down_sync(0xffffffffu, vely,   o);
        border += __shfl_down_sync(0xffffffffu, border, o);
        deadf  += __shfl_down_sync(0xffffffffu, deadf,  o);
        consf  += __shfl_down_sync(0xffffffffu, consf,  o);
    }
    if ((threadIdx.x & 31) == 0) {
        atomicAdd(&g_red[0], (double)velx);
        atomicAdd(&g_red[1], (double)vely);
        atomicAdd(&g_red[2], (double)border);
        atomicAdd(&g_red[3], (double)deadf);
        atomicAdd(&g_red[4], (double)consf);
    }
}

// ---------------- Kernel 3: scalar outputs ----------------
__global__ void final_kernel(float* __restrict__ out, int base, float invN)
{
    if (threadIdx.x == 0 && blockIdx.x == 0) {
        out[base + 0] = (float)g_red[0] * invN;   // velocity_bonus x (mean)
        out[base + 1] = (float)g_red[1] * invN;   // velocity_bonus y
        out[base + 2] = (float)g_red[2];          // border_cost
        out[base + 3] = (float)g_red[4];          // food_reward (consumed count)
        out[base + 4] = (float)g_red[3];          // dead_cost
        out[base + 5] = (float)g_red[5];          // visible_food
        out[base + 6] = (float)g_red[6];          // mean_food_dist (sum)
    }
}

extern "C" void kernel_launch(void* const* d_in, const int* in_sizes, int n_in,
                              void* d_out, int out_size)
{
    const float* x      = (const float*)d_in[0];
    const int*   src    = (const int*)  d_in[1];
    const int*   dst    = (const int*)  d_in[2];
    const float* noise  = (const float*)d_in[3];
    const float* W_edge = (const float*)d_in[4];
    const float* W_src  = (const float*)d_in[5];
    const float* b1     = (const float*)d_in[6];
    const float* W_out  = (const float*)d_in[7];
    const float* b2     = (const float*)d_in[8];

    int n = in_sizes[0] / 10;
    int E = in_sizes[1];
    float* out = (float*)d_out;

    int scalarBase = out_size - 7;
    int keepBase   = scalarBase - n;

    prep_kernel<<<(n + 255) / 256, 256>>>(x, W_edge, W_src, b1, n);
    edge_kernel<<<592, 256>>>(src, dst, W_edge, W_out, E);
    node_kernel<<<(n + 255) / 256, 256>>>(x, noise, b2, out, n, keepBase);
    final_kernel<<<1, 32>>>(out, scalarBase, 1.0f / (float)n);
}

// round 16
// speedup vs baseline: 1.1951x; 1.0077x over previous
#include <cuda_runtime.h>
#include <cuda_fp16.h>

#define NN 50000
#define NE 3200000

// Scratch (device globals — no allocation allowed)
__device__ float4 g_nodeF4[NN];     // pos.x, pos.y, cell, pad
__device__ uint4  g_sh[NN * 2];     // s[16] fp16, 32B/node
__device__ float4 g_yacc[NN];       // sum over edges of m@W_out
__device__ float  g_degacc[NN];     // deg + 4096*consume_deg (exact ints)
__device__ double g_red[8];         // 0:velx 1:vely 2:border 3:dead 4:consumed 5:vis_food 6:food_dist

// ---------------- Kernel 0: prep, 2 threads per node (each does 8 hidden units) ----------------
__global__ void __launch_bounds__(256)
prep_kernel(const float* __restrict__ x,
            const float* __restrict__ W_edge,
            const float* __restrict__ W_src,
            const float* __restrict__ b1,
            int n)
{
    int t = blockIdx.x * blockDim.x + threadIdx.x;
    if (t == 0) {
        #pragma unroll
        for (int k = 0; k < 8; k++) g_red[k] = 0.0;
    }
    int i = t >> 1;        // node
    int q = t & 1;         // which half of the 16 hidden units
    if (i >= n) return;

    float xv[10];
    #pragma unroll
    for (int c = 0; c < 10; c++) xv[c] = __ldg(&x[i * 10 + c]);
    float cell = xv[4];

    // s_j = b1_j + cell*W_edge[3][j] + sum_c x_c * W_src[c][j]  (8 units per thread)
    float sv[8];
    #pragma unroll
    for (int jj = 0; jj < 8; jj++) {
        int j = q * 8 + jj;
        float acc = __ldg(&b1[j]) + cell * __ldg(&W_edge[3 * 16 + j]);
        #pragma unroll
        for (int c = 0; c < 10; c++)
            acc += xv[c] * __ldg(&W_src[c * 16 + j]);
        sv[jj] = acc;
    }

    uint4 pk;
    __half2 h0 = __floats2half2_rn(sv[0], sv[1]);
    __half2 h1 = __floats2half2_rn(sv[2], sv[3]);
    __half2 h2 = __floats2half2_rn(sv[4], sv[5]);
    __half2 h3 = __floats2half2_rn(sv[6], sv[7]);
    pk.x = *reinterpret_cast<unsigned int*>(&h0);
    pk.y = *reinterpret_cast<unsigned int*>(&h1);
    pk.z = *reinterpret_cast<unsigned int*>(&h2);
    pk.w = *reinterpret_cast<unsigned int*>(&h3);
    g_sh[i * 2 + q] = pk;

    if (q == 0) {
        g_nodeF4[i]  = make_float4(xv[0], xv[1], cell, 0.0f);
        g_yacc[i]    = make_float4(0.f, 0.f, 0.f, 0.f);
        g_degacc[i]  = 0.f;
    }
}

// ---------------- Kernel 1: edge kernel (2 edges/thread, smem weights, 1 resident wave) ----------------
__global__ void __launch_bounds__(256)
edge_kernel(const int* __restrict__ src,
            const int* __restrict__ dst,
            const float* __restrict__ W_edge,
            const float* __restrict__ W_out,
            int E)
{
    __shared__ float4 sWe[16];   // (wA, wB, wC, 0) per hidden unit
    __shared__ float4 sWo[16];   // W_out row per hidden unit

    if (threadIdx.x < 16) {
        int j = threadIdx.x;
        sWe[j] = make_float4(__ldg(&W_edge[0 * 16 + j]),
                             __ldg(&W_edge[1 * 16 + j]),
                             __ldg(&W_edge[2 * 16 + j]),
                             0.0f);
        sWo[j] = __ldg((const float4*)&W_out[j * 4]);
    }
    __syncthreads();

    const float4* __restrict__ nf  = g_nodeF4;
    const uint4*  __restrict__ spv = g_sh;
    const int2*   __restrict__ s2  = (const int2*)src;
    const int2*   __restrict__ d2v = (const int2*)dst;

    float vf = 0.f;   // visible_food count
    float fd = 0.f;   // food dist sum

    int P = E >> 1;   // edge pairs (E is even)
    int stride = gridDim.x * blockDim.x;
    for (int p = blockIdx.x * blockDim.x + threadIdx.x; p < P; p += stride) {
        int2 sp = __ldg(&s2[p]);
        int2 dp = __ldg(&d2v[p]);

        // issue ALL gathers up front (8 independent LDG.128)
        float4 nsa = __ldg(&nf[sp.x]);
        float4 nda = __ldg(&nf[dp.x]);
        uint4  pa0 = __ldg(&spv[sp.x * 2 + 0]);
        uint4  pa1 = __ldg(&spv[sp.x * 2 + 1]);
        float4 nsb = __ldg(&nf[sp.y]);
        float4 ndb = __ldg(&nf[dp.y]);
        uint4  pb0 = __ldg(&spv[sp.y * 2 + 0]);
        uint4  pb1 = __ldg(&spv[sp.y * 2 + 1]);

        float dxa = nsa.x - nda.x;
        float dya = nsa.y - nda.y;
        float dista = sqrtf(__fadd_rn(__fadd_rn(__fmul_rn(dxa, dxa), __fmul_rn(dya, dya)), 1e-12f));
        float dxb = nsb.x - ndb.x;
        float dyb = nsb.y - ndb.y;
        float distb = sqrtf(__fadd_rn(__fadd_rn(__fmul_rn(dxb, dxb), __fmul_rn(dyb, dyb)), 1e-12f));

        unsigned int pka[8] = {pa0.x, pa0.y, pa0.z, pa0.w, pa1.x, pa1.y, pa1.z, pa1.w};
        unsigned int pkb[8] = {pb0.x, pb0.y, pb0.z, pb0.w, pb1.x, pb1.y, pb1.z, pb1.w};

        float ya0 = 0.f, ya1 = 0.f, ya2 = 0.f, ya3 = 0.f;
        float yb0 = 0.f, yb1 = 0.f, yb2 = 0.f, yb3 = 0.f;

        // joint MLP loop: each weight LDS broadcast serves both edges
        #pragma unroll
        for (int q = 0; q < 8; q++) {
            float2 fa = __half22float2(*reinterpret_cast<__half2*>(&pka[q]));
            float2 fb = __half22float2(*reinterpret_cast<__half2*>(&pkb[q]));
            int j0 = q * 2, j1 = q * 2 + 1;
            float4 we0 = sWe[j0];
            float4 we1 = sWe[j1];
            float4 wo0 = sWo[j0];
            float4 wo1 = sWo[j1];

            float ga0 = fa.x + dista * we0.x + dxa * we0.y + dya * we0.z;
            float ga1 = fa.y + dista * we1.x + dxa * we1.y + dya * we1.z;
            float gb0 = fb.x + distb * we0.x + dxb * we0.y + dyb * we0.z;
            float gb1 = fb.y + distb * we1.x + dxb * we1.y + dyb * we1.z;
            float ma0 = fmaxf(ga0, 0.f);
            float ma1 = fmaxf(ga1, 0.f);
            float mb0 = fmaxf(gb0, 0.f);
            float mb1 = fmaxf(gb1, 0.f);

            ya0 += ma0 * wo0.x + ma1 * wo1.x;
            ya1 += ma0 * wo0.y + ma1 * wo1.y;
            ya2 += ma0 * wo0.z + ma1 * wo1.z;
            ya3 += ma0 * wo0.w + ma1 * wo1.w;
            yb0 += mb0 * wo0.x + mb1 * wo1.x;
            yb1 += mb0 * wo0.y + mb1 * wo1.y;
            yb2 += mb0 * wo0.z + mb1 * wo1.z;
            yb3 += mb0 * wo0.w + mb1 * wo1.w;
        }

        float4* ypa = &g_yacc[dp.x];
        asm volatile("red.global.add.v4.f32 [%0], {%1,%2,%3,%4};"
                     :: "l"(ypa), "f"(ya0), "f"(ya1), "f"(ya2), "f"(ya3) : "memory");
        bool consumea = (dista < 0.05f) && (nsa.z == 1.0f) && (nda.z == 0.0f);
        atomicAdd(&g_degacc[dp.x], consumea ? 4097.0f : 1.0f);
        if (nsa.z == 0.0f) { vf += 1.0f; fd += dista; }

        float4* ypb = &g_yacc[dp.y];
        asm volatile("red.global.add.v4.f32 [%0], {%1,%2,%3,%4};"
                     :: "l"(ypb), "f"(yb0), "f"(yb1), "f"(yb2), "f"(yb3) : "memory");
        bool consumeb = (distb < 0.05f) && (nsb.z == 1.0f) && (ndb.z == 0.0f);
        atomicAdd(&g_degacc[dp.y], consumeb ? 4097.0f : 1.0f);
        if (nsb.z == 0.0f) { vf += 1.0f; fd += distb; }
    }

    // warp reduce, lane0 -> double atomics
    #pragma unroll
    for (int o = 16; o > 0; o >>= 1) {
        vf += __shfl_down_sync(0xffffffffu, vf, o);
        fd += __shfl_down_sync(0xffffffffu, fd, o);
    }
    if ((threadIdx.x & 31) == 0) {
        atomicAdd(&g_red[5], (double)vf);
        atomicAdd(&g_red[6], (double)fd);
    }
}

// ---------------- Kernel 2: node finalize ----------------
__global__ void node_kernel(const float* __restrict__ x,
                            const float* __restrict__ noise,
                            const float* __restrict__ b2,
                            float* __restrict__ out,
                            int n, int keepBase)
{
    int i = blockIdx.x * blockDim.x + threadIdx.x;

    float velx = 0.f, vely = 0.f, border = 0.f, deadf = 0.f, consf = 0.f;

    if (i < n) {
        float4 y   = g_yacc[i];
        float pack = g_degacc[i];

        float xv[10];
        #pragma unroll
        for (int c = 0; c < 10; c++) xv[c] = __ldg(&x[i * 10 + c]);
        float cell = xv[4];
        float cm = (cell == 1.0f) ? 1.0f : 0.0f;

        float h0 = tanhf(y.x + __ldg(&b2[0])) * cm;
        float h1 = tanhf(y.y + __ldg(&b2[1])) * cm;
        float h2 = tanhf(y.z + __ldg(&b2[2])) * cm;
        float h3 = tanhf(y.w + __ldg(&b2[3])) * cm;

        float nvx = fminf(fmaxf(xv[2] + h0 * 0.005f, -0.02f), 0.02f);
        float nvy = fminf(fmaxf(xv[3] + h1 * 0.005f, -0.02f), 0.02f);
        float npx = xv[0] + nvx;
        float npy = xv[1] + nvy;

        float nzx = nvx + (__ldg(&noise[2 * i])     * 2.0f - 1.0f) * 0.004f * cm;
        float nzy = nvy + (__ldg(&noise[2 * i + 1]) * 2.0f - 1.0f) * 0.004f * cm;

        float* o = out + (size_t)i * 10;
        o[0] = npx; o[1] = npy; o[2] = nzx; o[3] = nzy; o[4] = cell;
        o[5] = h2;  o[6] = h3;  o[7] = xv[7]; o[8] = xv[8]; o[9] = xv[9];

        int pi   = (int)pack;
        int deg  = pi & 4095;
        int cdeg = pi >> 12;
        bool dead     = (cell == 1.0f) && (deg < 3);
        bool consumed = (cell == 0.0f) && (cdeg >= 3);
        out[keepBase + i] = (dead || consumed) ? 0.0f : 1.0f;

        velx = fabsf(nvx);
        vely = fabsf(nvy);
        float apx = fabsf(npx);
        if (apx > 1.0f) border += logf(apx + 1e-6f);
        float apy = fabsf(npy);
        if (apy > 1.0f) border += logf(apy + 1e-6f);
        deadf = dead ? 1.0f : 0.0f;
        consf = consumed ? 1.0f : 0.0f;
    }

    #pragma unroll
    for (int o = 16; o > 0; o >>= 1) {
        velx   += __shfl_down_sync(0xffffffffu, velx,   o);
        vely   += __shfl_down_sync(0xffffffffu, vely,   o);
        border += __shfl_down_sync(0xffffffffu, border, o);
        deadf  += __shfl_down_sync(0xffffffffu, deadf,  o);
        consf  += __shfl_down_sync(0xffffffffu, consf,  o);
    }
    if ((threadIdx.x & 31) == 0) {
        atomicAdd(&g_red[0], (double)velx);
        atomicAdd(&g_red[1], (double)vely);
        atomicAdd(&g_red[2], (double)border);
        atomicAdd(&g_red[3], (double)deadf);
        atomicAdd(&g_red[4], (double)consf);
    }
}

// ---------------- Kernel 3: scalar outputs ----------------
__global__ void final_kernel(float* __restrict__ out, int base, float invN)
{
    if (threadIdx.x == 0 && blockIdx.x == 0) {
        out[base + 0] = (float)g_red[0] * invN;   // velocity_bonus x (mean)
        out[base + 1] = (float)g_red[1] * invN;   // velocity_bonus y
        out[base + 2] = (float)g_red[2];          // border_cost
        out[base + 3] = (float)g_red[4];          // food_reward (consumed count)
        out[base + 4] = (float)g_red[3];          // dead_cost
        out[base + 5] = (float)g_red[5];          // visible_food
        out[base + 6] = (float)g_red[6];          // mean_food_dist (sum)
    }
}

extern "C" void kernel_launch(void* const* d_in, const int* in_sizes, int n_in,
                              void* d_out, int out_size)
{
    const float* x      = (const float*)d_in[0];
    const int*   src    = (const int*)  d_in[1];
    const int*   dst    = (const int*)  d_in[2];
    const float* noise  = (const float*)d_in[3];
    const float* W_edge = (const float*)d_in[4];
    const float* W_src  = (const float*)d_in[5];
    const float* b1     = (const float*)d_in[6];
    const float* W_out  = (const float*)d_in[7];
    const float* b2     = (const float*)d_in[8];

    int n = in_sizes[0] / 10;
    int E = in_sizes[1];
    float* out = (float*)d_out;

    int scalarBase = out_size - 7;
    int keepBase   = scalarBase - n;

    prep_kernel<<<(2 * n + 255) / 256, 256>>>(x, W_edge, W_src, b1, n);
    edge_kernel<<<296, 256>>>(src, dst, W_edge, W_out, E);
    node_kernel<<<(n + 255) / 256, 256>>>(x, noise, b2, out, n, keepBase);
    final_kernel<<<1, 32>>>(out, scalarBase, 1.0f / (float)n);
}